// round 4
// baseline (speedup 1.0000x reference)
#include <cuda_runtime.h>

// ============================================================================
// 2-layer tanh RNN, B=32, L=2048, H=512 — persistent layer-pipelined kernel v3.
//
// 128 persistent CTAs (1/SM):
//   CTA 0..63   : layer 0, output columns [cta*8, cta*8+8)
//   CTA 64..127 : layer 1, columns [(cta-64)*8, ...)
// Weight slices in SMEM for the whole run (lane-interleaved float4,
// conflict-free LDS.128). K=512 split: lane ln owns k in [16*ln, 16*ln+16).
// Inputs read as float4 (coalesced LDG.128 / __ldcg). Partial sums reduced
// via padded SMEM transpose.
//
// Sync v3: per-CTA progress words (NO shared counter -> no 64-way L2 atomic
// serialization, which cost ~2x1750 cyc/step in v2):
//   producer: STG data -> __syncthreads -> tid0: fence.acq_rel.gpu +
//             st.relaxed.gpu g_prog[cta] = t+1
//   consumer: lanewise relaxed poll (lane ln watches prog[ln], prog[ln+32]),
//             __all_sync ballot, then fence.acq_rel.gpu
//
// Dataflow: layer-0 h -> 4-slot global ring; layer-1 h -> d_out directly.
// ============================================================================

#define BB 32
#define LL 2048
#define HH 512
#define GA 64
#define GB 64
#define NTHR 256

__device__ float g_ring[4 * BB * HH];   // layer-0 h ring, 256 KB
__device__ int   g_progA[GA];           // per-CTA: #steps completed (layer 0)
__device__ int   g_progB[GB];           // per-CTA: #steps completed (layer 1)

__device__ __forceinline__ void wait_group(const int* prog, int tgt, int ln) {
    const int* p0 = prog + ln;
    const int* p1 = prog + 32 + ln;
    while (true) {
        int v0, v1;
        asm volatile("ld.relaxed.gpu.global.b32 %0, [%1];" : "=r"(v0) : "l"(p0) : "memory");
        asm volatile("ld.relaxed.gpu.global.b32 %0, [%1];" : "=r"(v1) : "l"(p1) : "memory");
        if (__all_sync(0xffffffffu, (v0 >= tgt) && (v1 >= tgt))) break;
        __nanosleep(30);
    }
    asm volatile("fence.acq_rel.gpu;" ::: "memory");
}

__device__ __forceinline__ void publish_prog(int* slot, int val) {
    asm volatile("fence.acq_rel.gpu;" ::: "memory");
    asm volatile("st.relaxed.gpu.global.b32 [%0], %1;" :: "l"(slot), "r"(val) : "memory");
}

#define FMA2(d, a, w) asm volatile("fma.rn.f32x2 %0, %1, %2, %0;" \
                                   : "+l"(d) : "l"(a), "l"(w))

__device__ __forceinline__ unsigned long long pack2(float v) {
    unsigned long long r;
    asm("mov.b64 %0, {%1,%1};" : "=l"(r) : "f"(v));
    return r;
}

__global__ void zero_flags_kernel() {
    int i = threadIdx.x;
    if (i < GA) g_progA[i] = 0;
    else if (i < GA + GB) g_progB[i - GA] = 0;
}

// Accumulate one side into acc[16]. acc[b*4+q] packs output columns
// (2q, 2q+1) for batch row b0+b. Weights: lane-interleaved ulonglong2 arrays
// wA (cols 0-3), wB (cols 4-7), index [i*32+ln] holds k = 16*ln + i.
__device__ __forceinline__ void accum_side(
    unsigned long long acc[16],
    const ulonglong2* __restrict__ wA, const ulonglong2* __restrict__ wB,
    const float* __restrict__ p, long long stride, int b0, int ln, bool useL2)
{
    #pragma unroll
    for (int i4 = 0; i4 < 4; i4++) {
        float4 v[4];
        #pragma unroll
        for (int b = 0; b < 4; b++) {
            const float4* addr = (const float4*)(p + (long long)(b0 + b) * stride
                                                 + 16 * ln + 4 * i4);
            v[b] = useL2 ? __ldcg(addr) : *addr;
        }
        #pragma unroll
        for (int e = 0; e < 4; e++) {
            int i = 4 * i4 + e;
            ulonglong2 a  = wA[i * 32 + ln];
            ulonglong2 bq = wB[i * 32 + ln];
            #pragma unroll
            for (int b = 0; b < 4; b++) {
                float xv = (e == 0) ? v[b].x : (e == 1) ? v[b].y
                         : (e == 2) ? v[b].z : v[b].w;
                unsigned long long xp = pack2(xv);
                FMA2(acc[b * 4 + 0], xp, a.x);
                FMA2(acc[b * 4 + 1], xp, a.y);
                FMA2(acc[b * 4 + 2], xp, bq.x);
                FMA2(acc[b * 4 + 3], xp, bq.y);
            }
        }
    }
}

__global__ __launch_bounds__(NTHR) void rnn_kernel(
    const float* __restrict__ x,   const float* __restrict__ h0in,
    const float* __restrict__ Wi,  const float* __restrict__ bi,
    const float* __restrict__ Wh,  const float* __restrict__ bh,
    float* __restrict__ out, int write_final)
{
    extern __shared__ float smem[];
    float4* sWiA = (float4*)smem;          // [512] cols 0-3 of Wi slice
    float4* sWiB = sWiA + HH;              // [512] cols 4-7
    float4* sWhA = sWiB + HH;
    float4* sWhB = sWhA + HH;
    float*  red  = (float*)(sWhB + HH);    // [8 warps][32][33]

    const int  cta   = blockIdx.x;
    const bool isA   = (cta < GA);
    const int  layer = isA ? 0 : 1;
    const int  c0    = (isA ? cta : cta - GA) * 8;
    const int  tid   = threadIdx.x;
    const int  w     = tid >> 5;
    const int  ln    = tid & 31;

    // ---- stage weight slices (once), lane-interleaved layout ----
    {
        const float* wi_g = Wi + (size_t)layer * HH * HH + c0;
        const float* wh_g = Wh + (size_t)layer * HH * HH + c0;
        for (int k = tid; k < HH; k += NTHR) {
            int idx = (k & 15) * 32 + (k >> 4);   // [i][owner_lane]
            const float4* ri = (const float4*)(wi_g + (size_t)k * HH);
            const float4* rh = (const float4*)(wh_g + (size_t)k * HH);
            sWiA[idx] = ri[0];  sWiB[idx] = ri[1];
            sWhA[idx] = rh[0];  sWhB[idx] = rh[1];
        }
    }
    __syncthreads();

    const int   myb  = w * 4 + (ln >> 3);
    const int   myc  = c0 + (ln & 7);
    const float bias = bi[layer * HH + myc] + bh[layer * HH + myc];
    const int   b0   = w * 4;
    float* redw = red + w * (32 * 33);

    const ulonglong2* wiA = (const ulonglong2*)sWiA;
    const ulonglong2* wiB = (const ulonglong2*)sWiB;
    const ulonglong2* whA = (const ulonglong2*)sWhA;
    const ulonglong2* whB = (const ulonglong2*)sWhB;

    int* myprog = isA ? &g_progA[cta] : &g_progB[cta - GA];

    #pragma unroll 1
    for (int t = 0; t < LL; t++) {
        unsigned long long acc[16];
        #pragma unroll
        for (int i = 0; i < 16; i++) acc[i] = 0ull;

        if (isA) {
            // x-side first: ungated, hides the poll + gated-load latency.
            accum_side(acc, wiA, wiB, x + (long long)t * HH,
                       (long long)LL * HH, b0, ln, false);
            const float* ph; long long sh;
            if (t == 0) { ph = h0in; sh = HH; }
            else {
                wait_group(g_progA, t, ln);            // own group done t-1
                ph = g_ring + ((t - 1) & 3) * (BB * HH); sh = HH;
            }
            accum_side(acc, whA, whB, ph, sh, b0, ln, true);
            if (t >= 4) wait_group(g_progB, t - 3, ln); // ring slot t%4 free
        } else {
            // own-hidden side first (own group's t-1: almost always ready).
            const float* ph; long long sh;
            if (t == 0) { ph = h0in + BB * HH; sh = HH; }
            else {
                wait_group(g_progB, t, ln);
                ph = out + (long long)(t - 1) * HH; sh = (long long)LL * HH;
            }
            accum_side(acc, whA, whB, ph, sh, b0, ln, true);
            wait_group(g_progA, t + 1, ln);            // layer-0 done step t
            accum_side(acc, wiA, wiB, g_ring + (t & 3) * (BB * HH),
                       HH, b0, ln, true);
        }

        // ---- reduce over 32-lane K split (padded SMEM transpose) ----
        #pragma unroll
        for (int i = 0; i < 16; i++) {
            float2 v = *reinterpret_cast<float2*>(&acc[i]);
            int a = (i >> 2) * 8 + (i & 3) * 2;
            redw[ln * 33 + a]     = v.x;
            redw[ln * 33 + a + 1] = v.y;
        }
        __syncwarp();
        float s0 = 0.f, s1 = 0.f, s2 = 0.f, s3 = 0.f;
        #pragma unroll
        for (int a = 0; a < 32; a += 4) {
            s0 += redw[(a + 0) * 33 + ln];
            s1 += redw[(a + 1) * 33 + ln];
            s2 += redw[(a + 2) * 33 + ln];
            s3 += redw[(a + 3) * 33 + ln];
        }
        float hval = tanhf((s0 + s1) + (s2 + s3) + bias);
        __syncwarp();   // redw reusable next step (warp-private region)

        // ---- publish ----
        if (isA) {
            g_ring[(t & 3) * (BB * HH) + myb * HH + myc] = hval;
            if (write_final && t == LL - 1)
                out[(long long)BB * LL * HH + myb * HH + myc] = hval;
        } else {
            out[(long long)myb * LL * HH + (long long)t * HH + myc] = hval;
            if (write_final && t == LL - 1)
                out[(long long)BB * LL * HH + BB * HH + myb * HH + myc] = hval;
        }
        __syncthreads();                 // all STGs of this CTA issued
        if (tid == 0) publish_prog(myprog, t + 1);
    }
}

extern "C" void kernel_launch(void* const* d_in, const int* in_sizes, int n_in,
                              void* d_out, int out_size)
{
    const float* x  = (const float*)d_in[0];
    const float* h0 = (const float*)d_in[1];
    const float* Wi = (const float*)d_in[2];
    const float* bi = (const float*)d_in[3];
    const float* Wh = (const float*)d_in[4];
    const float* bh = (const float*)d_in[5];
    float* out = (float*)d_out;

    int write_final = (out_size >= BB * LL * HH + 2 * BB * HH) ? 1 : 0;

    size_t smem = (size_t)(4 * HH * 4 + 8 * 32 * 33) * sizeof(float); // ~66 KB
    cudaFuncSetAttribute(rnn_kernel,
                         cudaFuncAttributeMaxDynamicSharedMemorySize, (int)smem);

    zero_flags_kernel<<<1, 128>>>();
    rnn_kernel<<<GA + GB, NTHR, smem>>>(x, h0, Wi, bi, Wh, bh, out, write_final);
}

// round 5
// speedup vs baseline: 1.1777x; 1.1777x over previous
#include <cuda_runtime.h>

// ============================================================================
// 2-layer tanh RNN, B=32, L=2048, H=512 — merged phase-pipelined kernel v4.
//
// 128 persistent CTAs (1/SM). Each CTA owns 4 output columns of BOTH layers
// (cols [cta*4, cta*4+4)). Software pipeline over phases p = 0..L:
//   phase p computes  L0 step t=p (p<L)  and  L1 step t=p-1 (p>=1).
// Every dependency of phase p is produced in phase p-1, so there is exactly
// ONE chip-wide flag wait per phase (vs 2-3 in v2/v3).
//
// Sync: per-phase counter g_flag[p]. Producer: stores -> __syncthreads ->
// tid0 red.release.gpu.add. Consumer: WARP 0 ONLY polls ld.acquire.gpu
// (one coalesced same-address request per CTA per round), then __syncthreads
// releases the other warps (leader-acquire pattern, as in coop-groups grid
// sync). This kills the v2/v3 poll-traffic problem.
//
// Work split: 8 warps; warp w handles batch rows 4w..4w+3 for both layers.
// Lane ln owns k in [16ln, 16ln+16) (float4 loads). Weights stay in SMEM
// all run, lane-interleaved (conflict-free LDS.128). Partial sums reduced
// via padded 32x33 SMEM transpose (one transpose covers both layers).
// Compute: fp32 packed fma.rn.f32x2 (512 FMA2 per thread per phase).
//
// Dataflow: L0 h -> 2-slot global ring (slot p&1); L1 h -> d_out directly.
// Cross-SM reads use __ldcg (L2 is the coherence point).
// ============================================================================

#define BB 32
#define LL 2048
#define HH 512
#define NCTA 128
#define NTHR 256

__device__ float g_ring[2 * BB * HH];   // layer-0 h ring (2 slots, 128 KB)
__device__ int   g_flag[LL + 1];        // per-phase completion counters

__device__ __forceinline__ void wait_flag(const int* p, int tgt) {
    int v;
    while (true) {
        asm volatile("ld.acquire.gpu.global.b32 %0, [%1];"
                     : "=r"(v) : "l"(p) : "memory");
        if (v >= tgt) return;
        __nanosleep(20);
    }
}
__device__ __forceinline__ void rel_add(int* p) {
    asm volatile("red.release.gpu.global.add.u32 [%0], %1;"
                 :: "l"(p), "r"(1u) : "memory");
}

#define FMA2(d, a, w) asm volatile("fma.rn.f32x2 %0, %1, %2, %0;" \
                                   : "+l"(d) : "l"(a), "l"(w))

__device__ __forceinline__ unsigned long long pack2(float v) {
    unsigned long long r;
    asm("mov.b64 %0, {%1,%1};" : "=l"(r) : "f"(v));
    return r;
}

__global__ void zero_flags_kernel() {
    int i = blockIdx.x * blockDim.x + threadIdx.x;
    if (i < LL + 1) g_flag[i] = 0;
}

// Accumulate one matrix side for 4 rows x 4 cols into acc[8] (acc[r*2+cp]
// packs cols (2cp, 2cp+1) for row r0+r). Weights lane-interleaved:
// wgt[i*32+ln] = ulonglong2 = 4 cols of W at k = 16*ln + i.
__device__ __forceinline__ void accum4(
    unsigned long long* __restrict__ acc,
    const ulonglong2* __restrict__ wgt,
    const float* __restrict__ p, long long stride, int r0, int ln, bool cg)
{
    #pragma unroll
    for (int i4 = 0; i4 < 4; i4++) {
        float4 v[4];
        #pragma unroll
        for (int r = 0; r < 4; r++) {
            const float4* a = (const float4*)(p + (long long)(r0 + r) * stride
                                              + 16 * ln + 4 * i4);
            v[r] = cg ? __ldcg(a) : *a;
        }
        #pragma unroll
        for (int e = 0; e < 4; e++) {
            ulonglong2 wq = wgt[(4 * i4 + e) * 32 + ln];
            #pragma unroll
            for (int r = 0; r < 4; r++) {
                float xv = (e == 0) ? v[r].x : (e == 1) ? v[r].y
                         : (e == 2) ? v[r].z : v[r].w;
                unsigned long long xp = pack2(xv);
                FMA2(acc[r * 2 + 0], xp, wq.x);
                FMA2(acc[r * 2 + 1], xp, wq.y);
            }
        }
    }
}

__global__ __launch_bounds__(NTHR) void rnn_kernel(
    const float* __restrict__ x,   const float* __restrict__ h0in,
    const float* __restrict__ Wi,  const float* __restrict__ bi,
    const float* __restrict__ Wh,  const float* __restrict__ bh,
    float* __restrict__ out, int write_final)
{
    extern __shared__ float smem[];
    ulonglong2* sWi0 = (ulonglong2*)smem;        // [512] Wi layer0, 4 cols
    ulonglong2* sWh0 = sWi0 + HH;
    ulonglong2* sWi1 = sWh0 + HH;
    ulonglong2* sWh1 = sWi1 + HH;
    float*      red  = (float*)(sWh1 + HH);      // [8 warps][32][33]

    const int cta = blockIdx.x;
    const int tid = threadIdx.x;
    const int w   = tid >> 5;
    const int ln  = tid & 31;
    const int c0  = cta * 4;

    // ---- stage weight slices (once), lane-interleaved ----
    for (int k = tid; k < HH; k += NTHR) {
        int idx = (k & 15) * 32 + (k >> 4);
        sWi0[idx] = *(const ulonglong2*)(Wi + (size_t)k * HH + c0);
        sWh0[idx] = *(const ulonglong2*)(Wh + (size_t)k * HH + c0);
        sWi1[idx] = *(const ulonglong2*)(Wi + (size_t)HH * HH + (size_t)k * HH + c0);
        sWh1[idx] = *(const ulonglong2*)(Wh + (size_t)HH * HH + (size_t)k * HH + c0);
    }
    __syncthreads();

    // lane -> output mapping (after transpose reduce):
    //   layer = ln>>4, row = 4w + ((ln>>2)&3), col = c0 + (ln&3)
    const int   r0    = 4 * w;
    const int   layer = ln >> 4;
    const int   row   = r0 + ((ln >> 2) & 3);
    const int   col   = c0 + (ln & 3);
    const float biasv = bi[layer * HH + col] + bh[layer * HH + col];
    float* redw = red + w * (32 * 33);

    #pragma unroll 1
    for (int p = 0; p <= LL; p++) {
        unsigned long long acc[16];
        #pragma unroll
        for (int i = 0; i < 16; i++) acc[i] = 0ull;

        // --- ungated work first: L0 x-side (hides the flag wait) ---
        if (p < LL)
            accum4(acc, sWi0, x + (long long)p * HH, (long long)LL * HH,
                   r0, ln, false);

        // --- one chip-wide wait per phase (leader-acquire) ---
        if (p >= 1) {
            if (w == 0) wait_flag(&g_flag[p - 1], NCTA);
            __syncthreads();
        }

        // --- gated accumulations ---
        if (p < LL) {      // L0 hidden side: h0[p-1]
            const float* ph = (p == 0) ? h0in
                            : g_ring + ((p - 1) & 1) * (BB * HH);
            accum4(acc, sWh0, ph, HH, r0, ln, p != 0);
        }
        if (p >= 1) {      // L1 step t=p-1
            const float* ph1; long long sh1;
            if (p == 1) { ph1 = h0in + BB * HH;              sh1 = HH; }
            else        { ph1 = out + (long long)(p - 2) * HH; sh1 = (long long)LL * HH; }
            accum4(acc + 8, sWh1, ph1, sh1, r0, ln, true);
            accum4(acc + 8, sWi1, g_ring + ((p - 1) & 1) * (BB * HH),
                   HH, r0, ln, true);
        }

        // --- transpose-reduce over the 32-lane K split ---
        #pragma unroll
        for (int i = 0; i < 16; i++) {
            float2 v = *reinterpret_cast<float2*>(&acc[i]);
            int a = (i >> 3) * 16 + ((i >> 1) & 3) * 4 + (i & 1) * 2;
            redw[ln * 33 + a]     = v.x;
            redw[ln * 33 + a + 1] = v.y;
        }
        __syncwarp();
        float s0 = 0.f, s1 = 0.f, s2 = 0.f, s3 = 0.f;
        #pragma unroll
        for (int a = 0; a < 32; a += 4) {
            s0 += redw[(a + 0) * 33 + ln];
            s1 += redw[(a + 1) * 33 + ln];
            s2 += redw[(a + 2) * 33 + ln];
            s3 += redw[(a + 3) * 33 + ln];
        }
        float hval = tanhf((s0 + s1) + (s2 + s3) + biasv);
        __syncwarp();   // redw reusable next phase (warp-private)

        // --- publish ---
        if (layer == 0) {
            if (p < LL) {
                g_ring[(p & 1) * (BB * HH) + row * HH + col] = hval;
                if (p == LL - 1 && write_final)
                    out[(long long)BB * LL * HH + row * HH + col] = hval;
            }
        } else {
            if (p >= 1) {
                out[(long long)row * LL * HH + (long long)(p - 1) * HH + col] = hval;
                if (p == LL && write_final)
                    out[(long long)BB * LL * HH + BB * HH + row * HH + col] = hval;
            }
        }
        __syncthreads();                 // all stores of this CTA issued
        if (tid == 0) rel_add(&g_flag[p]);
    }
}

extern "C" void kernel_launch(void* const* d_in, const int* in_sizes, int n_in,
                              void* d_out, int out_size)
{
    const float* x  = (const float*)d_in[0];
    const float* h0 = (const float*)d_in[1];
    const float* Wi = (const float*)d_in[2];
    const float* bi = (const float*)d_in[3];
    const float* Wh = (const float*)d_in[4];
    const float* bh = (const float*)d_in[5];
    float* out = (float*)d_out;

    int write_final = (out_size >= BB * LL * HH + 2 * BB * HH) ? 1 : 0;

    size_t smem = (size_t)(4 * HH * 16) + (size_t)(8 * 32 * 33) * sizeof(float); // ~66 KB
    cudaFuncSetAttribute(rnn_kernel,
                         cudaFuncAttributeMaxDynamicSharedMemorySize, (int)smem);

    zero_flags_kernel<<<(LL + 1 + 255) / 256, 256>>>();
    rnn_kernel<<<NCTA, NTHR, smem>>>(x, h0, Wi, bi, Wh, bh, out, write_final);
}

// round 6
// speedup vs baseline: 2.0676x; 1.7556x over previous
#include <cuda_runtime.h>

// ============================================================================
// 2-layer tanh RNN, B=32, L=2048, H=512 — v5: v2 structure + sync fixes.
//
// 128 persistent CTAs (1/SM):
//   CTA 0..63   : layer 0 (group A), output columns [cta*8, cta*8+8)
//   CTA 64..127 : layer 1 (group B), columns [(cta-64)*8, ...)
// Weight slices in SMEM all run (lane-interleaved, conflict-free LDS.128).
// K mapping (NEW): lane ln owns k = 128*i4 + 4*ln + e, i4 in 0..3, e in 0..3.
//   -> a K-HALF (i4 in {0,1} or {2,3}) uses all 32 lanes, coalesced float4.
// Sync (NEW):
//   - A-CTAs 0..31 (cols < 256) publish flagAL[t]; A-CTAs 32..63 flagAH[t].
//     Consumers gate k<256 on flagAL and k>=256 on flagAH -> straggler spread
//     is pipelined instead of paid as max-of-64 every step.
//   - B-CTAs publish a single flagB[t] (own-side wait is never critical).
//   - Only WARP 0 polls (1 coalesced request/round, tight spin, no nanosleep);
//     __syncthreads releases the CTA. Publish: __syncthreads ->
//     tid0 red.release.gpu.add.
// Dataflow: L0 h -> 4-slot global ring; L1 h -> d_out directly. Cross-SM
// reads via __ldcg. Compute: fp32 packed fma.rn.f32x2, identical numerics.
// ============================================================================

#define BB 32
#define LL 2048
#define HH 512
#define GA 64
#define GB 64
#define NTHR 256

__device__ float g_ring[4 * BB * HH];   // layer-0 h ring, 256 KB
__device__ int   g_flagAL[LL];          // A cols [0,256)   done at step t
__device__ int   g_flagAH[LL];          // A cols [256,512) done at step t
__device__ int   g_flagB[LL];           // B done at step t

// Leader-warp wait: warp 0 spins (coalesced same-address acquire), then the
// caller's __syncthreads releases everyone. Call from ALL threads.
__device__ __forceinline__ void lead_wait(const int* p, int tgt, int w) {
    if (w == 0) {
        int v;
        do {
            asm volatile("ld.acquire.gpu.global.b32 %0, [%1];"
                         : "=r"(v) : "l"(p) : "memory");
        } while (v < tgt);
    }
    __syncthreads();
}
__device__ __forceinline__ void rel_add(int* p) {
    asm volatile("red.release.gpu.global.add.u32 [%0], %1;"
                 :: "l"(p), "r"(1u) : "memory");
}

#define FMA2(d, a, w) asm volatile("fma.rn.f32x2 %0, %1, %2, %0;" \
                                   : "+l"(d) : "l"(a), "l"(w))

__device__ __forceinline__ unsigned long long pack2(float v) {
    unsigned long long r;
    asm("mov.b64 %0, {%1,%1};" : "=l"(r) : "f"(v));
    return r;
}

__global__ void zero_flags_kernel() {
    int i = blockIdx.x * blockDim.x + threadIdx.x;
    if (i < LL) { g_flagAL[i] = 0; g_flagAH[i] = 0; g_flagB[i] = 0; }
}

// Accumulate one K-half (half = 0 -> k<256, half = 1 -> k>=256) of one side.
// acc[b*4+q] packs output columns (2q,2q+1) for batch row b0+b.
// Weights: wA holds cols 0-3, wB cols 4-7; index [(i4*4+e)*32 + ln] is
// k = 128*i4 + 4*ln + e. Loads batched up front for MLP.
__device__ __forceinline__ void accum_half(
    unsigned long long acc[16],
    const ulonglong2* __restrict__ wA, const ulonglong2* __restrict__ wB,
    const float* __restrict__ p, long long stride, int b0, int ln,
    int half, bool cg)
{
    float4 v[2][4];
    #pragma unroll
    for (int j = 0; j < 2; j++) {
        int i4 = 2 * half + j;
        #pragma unroll
        for (int b = 0; b < 4; b++) {
            const float4* a = (const float4*)(p + (long long)(b0 + b) * stride
                                              + 128 * i4 + 4 * ln);
            v[j][b] = cg ? __ldcg(a) : *a;
        }
    }
    #pragma unroll
    for (int j = 0; j < 2; j++) {
        int i4 = 2 * half + j;
        #pragma unroll
        for (int e = 0; e < 4; e++) {
            ulonglong2 a  = wA[(i4 * 4 + e) * 32 + ln];
            ulonglong2 bq = wB[(i4 * 4 + e) * 32 + ln];
            #pragma unroll
            for (int b = 0; b < 4; b++) {
                float xv = (e == 0) ? v[j][b].x : (e == 1) ? v[j][b].y
                         : (e == 2) ? v[j][b].z : v[j][b].w;
                unsigned long long xp = pack2(xv);
                FMA2(acc[b * 4 + 0], xp, a.x);
                FMA2(acc[b * 4 + 1], xp, a.y);
                FMA2(acc[b * 4 + 2], xp, bq.x);
                FMA2(acc[b * 4 + 3], xp, bq.y);
            }
        }
    }
}

__global__ __launch_bounds__(NTHR, 1) void rnn_kernel(
    const float* __restrict__ x,   const float* __restrict__ h0in,
    const float* __restrict__ Wi,  const float* __restrict__ bi,
    const float* __restrict__ Wh,  const float* __restrict__ bh,
    float* __restrict__ out, int write_final)
{
    extern __shared__ float smem[];
    ulonglong2* sWiA = (ulonglong2*)smem;      // [512] Wi cols 0-3 (16B each)
    ulonglong2* sWiB = sWiA + HH;              // [512] Wi cols 4-7
    ulonglong2* sWhA = sWiB + HH;
    ulonglong2* sWhB = sWhA + HH;
    float*      red  = (float*)(sWhB + HH);    // [8 warps][32][33]

    const int  cta   = blockIdx.x;
    const bool isA   = (cta < GA);
    const int  layer = isA ? 0 : 1;
    const int  c0    = (isA ? cta : cta - GA) * 8;
    const int  tid   = threadIdx.x;
    const int  w     = tid >> 5;
    const int  ln    = tid & 31;

    // ---- stage weight slices once: idx(k) = ((k>>7)*4 + (k&3))*32 + ((k>>2)&31)
    {
        const float* wi_g = Wi + (size_t)layer * HH * HH + c0;
        const float* wh_g = Wh + (size_t)layer * HH * HH + c0;
        for (int k = tid; k < HH; k += NTHR) {
            int idx = ((k >> 7) * 4 + (k & 3)) * 32 + ((k >> 2) & 31);
            const ulonglong2* ri = (const ulonglong2*)(wi_g + (size_t)k * HH);
            const ulonglong2* rh = (const ulonglong2*)(wh_g + (size_t)k * HH);
            sWiA[idx] = ri[0];  sWiB[idx] = ri[1];
            sWhA[idx] = rh[0];  sWhB[idx] = rh[1];
        }
    }
    __syncthreads();

    const int   myb  = w * 4 + (ln >> 3);
    const int   myc  = c0 + (ln & 7);
    const float bias = bi[layer * HH + myc] + bh[layer * HH + myc];
    const int   b0   = w * 4;
    float* redw = red + w * (32 * 33);

    #pragma unroll 1
    for (int t = 0; t < LL; t++) {
        unsigned long long acc[16];
        #pragma unroll
        for (int i = 0; i < 16; i++) acc[i] = 0ull;

        if (isA) {
            // x-side (ungated) first — both halves.
            const float* px = x + (long long)t * HH;
            accum_half(acc, sWiA, sWiB, px, (long long)LL * HH, b0, ln, 0, false);
            accum_half(acc, sWiA, sWiB, px, (long long)LL * HH, b0, ln, 1, false);
            // hidden side, half-gated.
            if (t == 0) {
                accum_half(acc, sWhA, sWhB, h0in, HH, b0, ln, 0, false);
                accum_half(acc, sWhA, sWhB, h0in, HH, b0, ln, 1, false);
            } else {
                const float* ph = g_ring + ((t - 1) & 3) * (BB * HH);
                lead_wait(&g_flagAL[t - 1], 32, w);
                accum_half(acc, sWhA, sWhB, ph, HH, b0, ln, 0, true);
                lead_wait(&g_flagAH[t - 1], 32, w);
                accum_half(acc, sWhA, sWhB, ph, HH, b0, ln, 1, true);
            }
        } else {
            // own hidden side first (single flag; own group, rarely critical).
            if (t == 0) {
                accum_half(acc, sWhA, sWhB, h0in + BB * HH, HH, b0, ln, 0, false);
                accum_half(acc, sWhA, sWhB, h0in + BB * HH, HH, b0, ln, 1, false);
            } else {
                lead_wait(&g_flagB[t - 1], GB, w);
                const float* ph = out + (long long)(t - 1) * HH;
                accum_half(acc, sWhA, sWhB, ph, (long long)LL * HH, b0, ln, 0, true);
                accum_half(acc, sWhA, sWhB, ph, (long long)LL * HH, b0, ln, 1, true);
            }
            // layer-0 output of step t, half-gated (pipelines A's stragglers).
            const float* pr = g_ring + (t & 3) * (BB * HH);
            lead_wait(&g_flagAL[t], 32, w);
            accum_half(acc, sWiA, sWiB, pr, HH, b0, ln, 0, true);
            lead_wait(&g_flagAH[t], 32, w);
            accum_half(acc, sWiA, sWiB, pr, HH, b0, ln, 1, true);
        }

        // ---- reduce over the 32-lane K split (padded SMEM transpose) ----
        #pragma unroll
        for (int i = 0; i < 16; i++) {
            float2 v = *reinterpret_cast<float2*>(&acc[i]);
            int a = (i >> 2) * 8 + (i & 3) * 2;
            redw[ln * 33 + a]     = v.x;
            redw[ln * 33 + a + 1] = v.y;
        }
        __syncwarp();
        float s0 = 0.f, s1 = 0.f, s2 = 0.f, s3 = 0.f;
        #pragma unroll
        for (int a = 0; a < 32; a += 4) {
            s0 += redw[(a + 0) * 33 + ln];
            s1 += redw[(a + 1) * 33 + ln];
            s2 += redw[(a + 2) * 33 + ln];
            s3 += redw[(a + 3) * 33 + ln];
        }
        float hval = tanhf((s0 + s1) + (s2 + s3) + bias);
        __syncwarp();   // redw reusable next step (warp-private)

        // ---- publish ----
        if (isA) {
            if (t >= 4) lead_wait(&g_flagB[t - 4], GB, w);  // ring slot free
            g_ring[(t & 3) * (BB * HH) + myb * HH + myc] = hval;
            if (write_final && t == LL - 1)
                out[(long long)BB * LL * HH + myb * HH + myc] = hval;
        } else {
            out[(long long)myb * LL * HH + (long long)t * HH + myc] = hval;
            if (write_final && t == LL - 1)
                out[(long long)BB * LL * HH + BB * HH + myb * HH + myc] = hval;
        }
        __syncthreads();                 // all STGs of this CTA issued
        if (tid == 0) {
            if (isA) rel_add(cta < 32 ? &g_flagAL[t] : &g_flagAH[t]);
            else     rel_add(&g_flagB[t]);
        }
    }
}

extern "C" void kernel_launch(void* const* d_in, const int* in_sizes, int n_in,
                              void* d_out, int out_size)
{
    const float* x  = (const float*)d_in[0];
    const float* h0 = (const float*)d_in[1];
    const float* Wi = (const float*)d_in[2];
    const float* bi = (const float*)d_in[3];
    const float* Wh = (const float*)d_in[4];
    const float* bh = (const float*)d_in[5];
    float* out = (float*)d_out;

    int write_final = (out_size >= BB * LL * HH + 2 * BB * HH) ? 1 : 0;

    size_t smem = (size_t)(4 * HH * 16) + (size_t)(8 * 32 * 33) * sizeof(float); // ~66 KB
    cudaFuncSetAttribute(rnn_kernel,
                         cudaFuncAttributeMaxDynamicSharedMemorySize, (int)smem);

    zero_flags_kernel<<<(LL + 255) / 256, 256>>>();
    rnn_kernel<<<GA + GB, NTHR, smem>>>(x, h0, Wi, bi, Wh, bh, out, write_final);
}